// round 5
// baseline (speedup 1.0000x reference)
#include <cuda_runtime.h>

#define N 4096
#define NN (N*N)
#define CIN 64
#define COUT 64
#define RWR 4
#define ITERS 10
#define JB 32          // persistent-kernel blocks (co-resident on 148 SMs)
#define JT 256
#define MAXE (1<<20)

// ---------------- device scratch (static globals: no allocations) ----------------
__device__ __align__(16) float g_L[NN];       // 64MB Jacobi working matrix (fits L2)
__device__ int   g_rowcnt[N];
__device__ int   g_cursor[N];
__device__ int   g_rowoff[N+1];
__device__ int   g_cols[MAXE];
__device__ __align__(16) float g_dinv[N];
__device__ __align__(16) float g_aux[N*CIN];
__device__ float g_G1[CIN*COUT];              // [i][o]
__device__ int   g_is64;
__device__ int   g_rotk[ITERS], g_rotl[ITERS];
__device__ float g_rotc[ITERS], g_rots[ITERS];
__device__ float g_rowval[N];
__device__ int   g_rowidx[N];
__device__ int   g_rlist[N];
__device__ int   g_rn;
__device__ unsigned g_barcnt;
__device__ volatile unsigned g_barsense;

__device__ __forceinline__ int edge_at(const int* e, int j) {
    return g_is64 ? e[2*j] : e[j];      // int64: value in low word
}

__device__ __forceinline__ void lexmax(float& bv, int& bi, float v, int i) {
    if (v > bv || (v == bv && i < bi)) { bv = v; bi = i; }
}

// software grid barrier (sense-reversing). All JB blocks must call uniformly.
__device__ __forceinline__ void gbar(unsigned& sense) {
    __syncthreads();
    sense ^= 1u;
    if (threadIdx.x == 0) {
        __threadfence();
        if (atomicAdd(&g_barcnt, 1u) == JB - 1u) {
            g_barcnt = 0u;
            __threadfence();
            g_barsense = sense;
        } else {
            while (g_barsense != sense) __nanosleep(32);
        }
    }
    __syncthreads();
    __threadfence();
}

// ---------------- setup ----------------
__global__ void k_setup(const int* e) {
    int t = blockIdx.x*blockDim.x + threadIdx.x;
    if (t < N) { g_rowcnt[t] = 0; g_cursor[t] = 0; }
    if (t == 0) {
        int nz = 0;
        for (int j = 1; j < 512; j += 2) nz |= (e[j] != 0);
        g_is64 = nz ? 0 : 1;
        g_rn = 0; g_barcnt = 0u; g_barsense = 0u;
    }
}

__global__ void k_count(const int* e, int E) {
    for (int j = blockIdx.x*blockDim.x + threadIdx.x; j < E; j += gridDim.x*blockDim.x)
        atomicAdd(&g_rowcnt[edge_at(e, j)], 1);
}

// single-block prefix scan (row offsets) + dinv
__global__ void k_scan() {
    __shared__ int sh[N];
    int tid = threadIdx.x;
    for (int i = tid; i < N; i += 1024) sh[i] = g_rowcnt[i];
    __syncthreads();
    for (int off = 1; off < N; off <<= 1) {
        int v[4];
#pragma unroll
        for (int r = 0; r < 4; r++) { int i = tid + r*1024; v[r] = (i >= off) ? sh[i-off] : 0; }
        __syncthreads();
#pragma unroll
        for (int r = 0; r < 4; r++) { int i = tid + r*1024; sh[i] += v[r]; }
        __syncthreads();
    }
    for (int i = tid; i < N; i += 1024) g_rowoff[i+1] = sh[i];
    if (tid == 0) g_rowoff[0] = 0;
    for (int i = tid; i < N; i += 1024) {
        float d = (float)g_rowcnt[i];
        g_dinv[i] = (d > 0.0f) ? __fdiv_rn(1.0f, __fsqrt_rn(d)) : 0.0f;
    }
}

__global__ void k_fill(const int* e, int E) {
    for (int j = blockIdx.x*blockDim.x + threadIdx.x; j < E; j += gridDim.x*blockDim.x) {
        int r = edge_at(e, j);
        int c = edge_at(e, E + j);
        int p = atomicAdd(&g_cursor[r], 1);
        g_cols[g_rowoff[r] + p] = c;
    }
}

// Write L from scratch (no zero, no 64MB read): per-row shared-count build.
// L[i][j] = (i==j) - (dinv_i*cnt)*dinv_j  (reference op order, RN). Fused per-row lexmax.
__global__ void k_transform_rowmax() {
    __shared__ __align__(16) float cnt[N];   // 16KB
    __shared__ float sv[256];
    __shared__ int   si[256];
    int i = blockIdx.x, tid = threadIdx.x;
    for (int j = tid; j < N; j += 256) cnt[j] = 0.0f;
    __syncthreads();
    int s0 = g_rowoff[i], s1 = g_rowoff[i+1];
    for (int p = s0 + tid; p < s1; p += 256) atomicAdd(&cnt[g_cols[p]], 1.0f);
    __syncthreads();
    float di = g_dinv[i];
    float4* row = (float4*)(g_L + (size_t)i*N);
    const float4* dv4 = (const float4*)g_dinv;
    float best = -1.0f; int bcol = 0x7FFFFFFF;
    for (int t4 = tid; t4 < N/4; t4 += 256) {
        int j = t4*4;
        float4 dj = dv4[t4];
        float4 cv = *((float4*)&cnt[j]);
        float4 o;
        o.x = __fsub_rn((i==j  )?1.0f:0.0f, __fmul_rn(__fmul_rn(di, cv.x), dj.x));
        o.y = __fsub_rn((i==j+1)?1.0f:0.0f, __fmul_rn(__fmul_rn(di, cv.y), dj.y));
        o.z = __fsub_rn((i==j+2)?1.0f:0.0f, __fmul_rn(__fmul_rn(di, cv.z), dj.z));
        o.w = __fsub_rn((i==j+3)?1.0f:0.0f, __fmul_rn(__fmul_rn(di, cv.w), dj.w));
        row[t4] = o;
        if (j+0 > i) lexmax(best, bcol, fabsf(o.x), j+0);
        if (j+1 > i) lexmax(best, bcol, fabsf(o.y), j+1);
        if (j+2 > i) lexmax(best, bcol, fabsf(o.z), j+2);
        if (j+3 > i) lexmax(best, bcol, fabsf(o.w), j+3);
    }
    sv[tid] = best; si[tid] = bcol;
    __syncthreads();
    for (int off = 128; off > 0; off >>= 1) {
        if (tid < off) {
            float v = sv[tid+off]; int c = si[tid+off];
            if (v > sv[tid] || (v == sv[tid] && c < si[tid])) { sv[tid] = v; si[tid] = c; }
        }
        __syncthreads();
    }
    if (tid == 0) { g_rowval[i] = sv[0]; g_rowidx[i] = si[0]; }
}

// ---------------- Cayley filter helper ----------------
__device__ __forceinline__ float g_entry(float wv, float hoi,
                                         const float* rw, const float* iw, float cval) {
    float hw = __fmul_rn(hoi, wv);
    float a2 = (hw > 1e-5f) ? 2.0f * atanf(__fdiv_rn(1.0f, hw)) : 2.0f;
    float acc = cval;
#pragma unroll
    for (int r = 0; r < RWR; r++) {
        float th = a2 * (float)(r + 1);
        float sn, cs;
        sincosf(th, &sn, &cs);
        acc += rw[r]*cs - iw[r]*sn;
    }
    return acc;
}

// ---------------- persistent Jacobi loop + tail (G1, aux copy, auxrot) ----------------
__global__ void __launch_bounds__(JT, 1) k_jacobi(const float* h, const float* rw,
        const float* iw, const float* cc, const float* x) {
    const int tid = threadIdx.x, bid = blockIdx.x;
    const int gt = bid*JT + tid;
    unsigned sense = 0u;
    __shared__ float sv[JT];
    __shared__ int   si[JT];

    for (int it = 0; it < ITERS; it++) {
        // ---- Phase A: global argmax + rotation params (block 0) ----
        if (bid == 0) {
            float best = -1.0f; int bflat = 0x7FFFFFFF;
            for (int i = tid; i < N; i += JT) {
                float v = __ldcg(&g_rowval[i]);
                if (v >= 0.0f) {
                    int flat = i*N + __ldcg(&g_rowidx[i]);
                    if (v > best || (v == best && flat < bflat)) { best = v; bflat = flat; }
                }
            }
            sv[tid] = best; si[tid] = bflat;
            __syncthreads();
            for (int off = JT/2; off > 0; off >>= 1) {
                if (tid < off) {
                    float v = sv[tid+off]; int f = si[tid+off];
                    if (v > sv[tid] || (v == sv[tid] && f < si[tid])) { sv[tid] = v; si[tid] = f; }
                }
                __syncthreads();
            }
            if (tid == 0) {
                int idx = si[0];
                int k = idx >> 12, l = idx & (N-1);
                float akl = __ldcg(&g_L[k*N + l]);
                float akk = __ldcg(&g_L[k*N + k]);
                float all = __ldcg(&g_L[l*N + l]);
                float aDiff = __fsub_rn(all, akk);
                float akl_safe   = (akl   == 0.0f) ? 1.0f : akl;
                float aDiff_safe = (aDiff == 0.0f) ? 1.0f : aDiff;
                float phi = __fdiv_rn(aDiff, __fmul_rn(2.0f, akl_safe));
                float t2 = __fdiv_rn(1.0f, __fadd_rn(fabsf(phi),
                             __fsqrt_rn(__fadd_rn(__fmul_rn(phi, phi), 1.0f))));
                if (phi < 0.0f) t2 = -t2;
                float t1 = __fdiv_rn(akl, aDiff_safe);
                float tt = (fabsf(akl) < __fmul_rn(fabsf(aDiff), 1e-36f)) ? t1 : t2;
                float cv = __fdiv_rn(1.0f, __fsqrt_rn(__fadd_rn(__fmul_rn(tt, tt), 1.0f)));
                float ss = __fmul_rn(tt, cv);
                g_rotk[it] = k; g_rotl[it] = l; g_rotc[it] = cv; g_rots[it] = ss;
                g_rn = 0;
            }
        }
        gbar(sense);

        // ---- Phase B: two-sided rotation + incremental rowmax ----
        {
            int k = __ldcg(&g_rotk[it]), l = __ldcg(&g_rotl[it]);
            float c = __ldcg(&g_rotc[it]), s = __ldcg(&g_rots[it]);
            int i = gt;
            if (i < N) {
                if (i != k && i != l) {
                    float ck = __ldcg(&g_L[i*N + k]), cl = __ldcg(&g_L[i*N + l]);
                    float nk = __fsub_rn(__fmul_rn(c, ck), __fmul_rn(s, cl));
                    float nl = __fadd_rn(__fmul_rn(s, ck), __fmul_rn(c, cl));
                    g_L[i*N + k] = nk;
                    g_L[i*N + l] = nl;
                    float rk = __ldcg(&g_L[k*N + i]), rl = __ldcg(&g_L[l*N + i]);
                    g_L[k*N + i] = __fsub_rn(__fmul_rn(c, rk), __fmul_rn(s, rl));
                    g_L[l*N + i] = __fadd_rn(__fmul_rn(s, rk), __fmul_rn(c, rl));
                    float bv = __ldcg(&g_rowval[i]); int bj = __ldcg(&g_rowidx[i]);
                    if (bj == k || bj == l) {
                        int p = atomicAdd(&g_rn, 1);
                        g_rlist[p] = i;
                    } else {
                        bool ch = false;
                        if (k > i) { float a = fabsf(nk); if (a > bv || (a == bv && k < bj)) { bv = a; bj = k; ch = true; } }
                        if (l > i) { float a = fabsf(nl); if (a > bv || (a == bv && l < bj)) { bv = a; bj = l; ch = true; } }
                        if (ch) { g_rowval[i] = bv; g_rowidx[i] = bj; }
                    }
                } else if (i == k) {
                    float akk = __ldcg(&g_L[k*N + k]), akl = __ldcg(&g_L[k*N + l]);
                    float alk = __ldcg(&g_L[l*N + k]), all = __ldcg(&g_L[l*N + l]);
                    float akk1 = __fsub_rn(__fmul_rn(c, akk), __fmul_rn(s, akl));
                    float akl1 = __fadd_rn(__fmul_rn(s, akk), __fmul_rn(c, akl));
                    float alk1 = __fsub_rn(__fmul_rn(c, alk), __fmul_rn(s, all));
                    float all1 = __fadd_rn(__fmul_rn(s, alk), __fmul_rn(c, all));
                    float akk2 = __fsub_rn(__fmul_rn(c, akk1), __fmul_rn(s, alk1));
                    float all2 = __fadd_rn(__fmul_rn(s, akl1), __fmul_rn(c, all1));
                    g_L[k*N + k] = akk2;
                    g_L[l*N + l] = all2;
                    g_L[k*N + l] = 0.0f;
                    g_L[l*N + k] = 0.0f;
                    int p = atomicAdd(&g_rn, 2);
                    g_rlist[p] = k; g_rlist[p+1] = l;
                }
            }
        }
        gbar(sense);

        // ---- Phase C: rescan flagged rows ----
        if (it < ITERS - 1) {
            int nr = __ldcg(&g_rn);
            for (int b = bid; b < nr; b += JB) {
                int i = __ldcg(&g_rlist[b]);
                const float* rowp = g_L + (size_t)i*N;
                float best = -1.0f; int bcol = 0x7FFFFFFF;
                for (int j = i + 1 + tid; j < N; j += JT) {
                    float a = fabsf(__ldcg(&rowp[j]));
                    if (a > best || (a == best && j < bcol)) { best = a; bcol = j; }
                }
                sv[tid] = best; si[tid] = bcol;
                __syncthreads();
                for (int off = JT/2; off > 0; off >>= 1) {
                    if (tid < off) {
                        float v = sv[tid+off]; int cI = si[tid+off];
                        if (v > sv[tid] || (v == sv[tid] && cI < si[tid])) { sv[tid] = v; si[tid] = cI; }
                    }
                    __syncthreads();
                }
                if (tid == 0) { g_rowval[i] = sv[0]; g_rowidx[i] = si[0]; }
                __syncthreads();
            }
            gbar(sense);
        }
    }

    // ---- tail: aux = x copy (all blocks) ----
    {
        const float4* xi = (const float4*)x;
        float4* ao = (float4*)g_aux;
        for (int i = gt; i < N*CIN/4; i += JB*JT) ao[i] = xi[i];
    }
    // G1 (block 1) — independent of aux
    if (bid == 1) {
        for (int t = tid; t < COUT*CIN; t += JT) {
            int o = t >> 6, i2 = t & 63;
            int oi = o*CIN + i2;
            g_G1[i2*COUT + o] = g_entry(1.0f, h[oi], rw + oi*RWR, iw + oi*RWR, cc[oi]);
        }
    }
    gbar(sense);
    // auxrot (block 0): aux = U^T x, apply R1^T first; per-column independence
    if (bid == 0 && tid < CIN) {
        int o = tid;
        for (int t = 0; t < ITERS; t++) {
            int k = g_rotk[t], l = g_rotl[t];
            float c = g_rotc[t], s = g_rots[t];
            float xk = __ldcg(&g_aux[k*CIN + o]), xl = __ldcg(&g_aux[l*CIN + o]);
            g_aux[k*CIN + o] = c*xk - s*xl;
            g_aux[l*CIN + o] = s*xk + c*xl;
        }
    }
}

// ---------------- gemm with inline special-node path; writes out + bias ----------------
__global__ void k_gemm(const float* h, const float* rw, const float* iw,
                       const float* cc, const float* bias, float* out) {
    __shared__ float sa[4][CIN];
    int tid = threadIdx.x;
    int r = tid >> 6, o = tid & 63;
    int n = blockIdx.x*4 + r;
    sa[r][o] = g_aux[n*CIN + o];
    __syncthreads();
    float wv = g_L[(size_t)n*N + n];
    float acc = 0.0f;
    if (wv == 1.0f) {
#pragma unroll 16
        for (int i = 0; i < CIN; i++)
            acc = fmaf(g_G1[i*COUT + o], sa[r][i], acc);
    } else {
        for (int i = 0; i < CIN; i++) {
            int oi = o*CIN + i;
            acc = fmaf(g_entry(wv, h[oi], rw + oi*RWR, iw + oi*RWR, cc[oi]), sa[r][i], acc);
        }
    }
    out[n*COUT + o] = acc + bias[o];
}

// output rows rotated in place (bias compensated; bias is zeros so exact)
__global__ void k_outrot(float* out, const float* bias) {
    int o = threadIdx.x;
    float b = bias[o];
    for (int t = ITERS - 1; t >= 0; t--) {
        int k = g_rotk[t], l = g_rotl[t];
        float c = g_rotc[t], s = g_rots[t];
        float vk = out[k*COUT + o] - b, vl = out[l*COUT + o] - b;
        out[k*COUT + o] =  c*vk + s*vl + b;
        out[l*COUT + o] = -s*vk + c*vl + b;
    }
}

// ---------------- launch ----------------
extern "C" void kernel_launch(void* const* d_in, const int* in_sizes, int n_in,
                              void* d_out, int out_size) {
    const float* x    = (const float*)d_in[0];
    const int*   e    = (const int*)  d_in[1];
    const float* rw   = (const float*)d_in[2];
    const float* iw   = (const float*)d_in[3];
    const float* h    = (const float*)d_in[4];
    const float* cc   = (const float*)d_in[5];
    const float* bias = (const float*)d_in[6];
    float* out = (float*)d_out;
    int E = in_sizes[1] / 2;   // edge_index shape (2, E)

    k_setup<<<16, 256>>>(e);
    k_count<<<256, 256>>>(e, E);
    k_scan<<<1, 1024>>>();
    k_fill<<<256, 256>>>(e, E);
    k_transform_rowmax<<<N, 256>>>();
    k_jacobi<<<JB, JT>>>(h, rw, iw, cc, x);
    k_gemm<<<N/4, 256>>>(h, rw, iw, cc, bias, out);
    k_outrot<<<1, 64>>>(out, bias);
}

// round 6
// speedup vs baseline: 1.0053x; 1.0053x over previous
#include <cuda_runtime.h>

#define N 4096
#define NN (N*N)
#define CIN 64
#define COUT 64
#define RWR 4
#define ITERS 10
#define MAXE (1<<20)
#define RB 256          // rescan_argmax blocks
#define TB 4096         // transform blocks (one per row)

// ---------------- device scratch (static globals: no allocations) ----------------
__device__ __align__(16) float g_L[NN];       // 64MB Jacobi working matrix
__device__ int   g_rowcnt[N];
__device__ int   g_cursor[N];
__device__ int   g_rowoff[N+1];
__device__ int   g_cols[MAXE];
__device__ __align__(16) float g_dinv[N];
__device__ __align__(16) float g_aux[N*CIN];
__device__ float g_G1[CIN*COUT];              // [i][o]
__device__ int   g_is64;
__device__ int   g_rotk[ITERS], g_rotl[ITERS];
__device__ float g_rotc[ITERS], g_rots[ITERS];
__device__ float g_rowval[N];
__device__ int   g_rowidx[N];
__device__ int   g_rlist[N];
__device__ int   g_rn;
__device__ unsigned g_arrT, g_arrR, g_arrG;   // arrival counters (reset by last block)

__device__ __forceinline__ int edge_at(const int* e, int j) {
    return g_is64 ? e[2*j] : e[j];      // int64: value in low word
}

__device__ __forceinline__ void lexmax(float& bv, int& bi, float v, int i) {
    if (v > bv || (v == bv && i < bi)) { bv = v; bi = i; }
}

// shared lexmax tree reduction over blockDim.x entries
__device__ __forceinline__ void block_lexmax(float* sv, int* si, int tid, int nthr) {
    for (int off = nthr/2; off > 0; off >>= 1) {
        if (tid < off) {
            float v = sv[tid+off]; int c = si[tid+off];
            if (v > sv[tid] || (v == sv[tid] && c < si[tid])) { sv[tid] = v; si[tid] = c; }
        }
        __syncthreads();
    }
}

// argmax over g_rowval + rotation-parameter computation (reference RN arithmetic).
// Call from one block; rowvals read via __ldcg (L2 coherence point).
__device__ __forceinline__ void argmax_and_params(int it, float* sv, int* si, int tid, int nthr) {
    float best = -1.0f; int bflat = 0x7FFFFFFF;
    for (int i = tid; i < N; i += nthr) {
        float v = __ldcg(&g_rowval[i]);
        if (v >= 0.0f) {
            int flat = i*N + __ldcg(&g_rowidx[i]);
            if (v > best || (v == best && flat < bflat)) { best = v; bflat = flat; }
        }
    }
    sv[tid] = best; si[tid] = bflat;
    __syncthreads();
    block_lexmax(sv, si, tid, nthr);
    if (tid == 0) {
        int idx = si[0];
        int k = idx >> 12, l = idx & (N-1);
        float akl = __ldcg(&g_L[k*N + l]);
        float akk = __ldcg(&g_L[k*N + k]);
        float all = __ldcg(&g_L[l*N + l]);
        float aDiff = __fsub_rn(all, akk);
        float akl_safe   = (akl   == 0.0f) ? 1.0f : akl;
        float aDiff_safe = (aDiff == 0.0f) ? 1.0f : aDiff;
        float phi = __fdiv_rn(aDiff, __fmul_rn(2.0f, akl_safe));
        float t2 = __fdiv_rn(1.0f, __fadd_rn(fabsf(phi),
                     __fsqrt_rn(__fadd_rn(__fmul_rn(phi, phi), 1.0f))));
        if (phi < 0.0f) t2 = -t2;
        float t1 = __fdiv_rn(akl, aDiff_safe);
        float tt = (fabsf(akl) < __fmul_rn(fabsf(aDiff), 1e-36f)) ? t1 : t2;
        float cv = __fdiv_rn(1.0f, __fsqrt_rn(__fadd_rn(__fmul_rn(tt, tt), 1.0f)));
        float ss = __fmul_rn(tt, cv);
        g_rotk[it] = k; g_rotl[it] = l; g_rotc[it] = cv; g_rots[it] = ss;
        g_rn = 0;
    }
}

// ---------------- setup ----------------
__global__ void k_setup(const int* e) {
    int t = blockIdx.x*blockDim.x + threadIdx.x;
    if (t < N) { g_rowcnt[t] = 0; g_cursor[t] = 0; }
    if (t == 0) {
        int nz = 0;
        for (int j = 1; j < 512; j += 2) nz |= (e[j] != 0);
        g_is64 = nz ? 0 : 1;
        g_rn = 0; g_arrT = 0u; g_arrR = 0u; g_arrG = 0u;
    }
}

// edge_index rows: row0 = [src;dst], row1 = [dst;src]. Reading the first half of
// both rows gives each undirected pair once; emit both (s,d) and (d,s).
__global__ void k_count(const int* e, int E) {
    int Eh = E >> 1;
    for (int j = blockIdx.x*blockDim.x + threadIdx.x; j < Eh; j += gridDim.x*blockDim.x) {
        int s = edge_at(e, j);
        int d = edge_at(e, E + j);
        atomicAdd(&g_rowcnt[s], 1);
        atomicAdd(&g_rowcnt[d], 1);
    }
}

// single-block prefix scan (row offsets) + dinv
__global__ void k_scan() {
    __shared__ int sh[N];
    int tid = threadIdx.x;
    for (int i = tid; i < N; i += 1024) sh[i] = g_rowcnt[i];
    __syncthreads();
    for (int off = 1; off < N; off <<= 1) {
        int v[4];
#pragma unroll
        for (int r = 0; r < 4; r++) { int i = tid + r*1024; v[r] = (i >= off) ? sh[i-off] : 0; }
        __syncthreads();
#pragma unroll
        for (int r = 0; r < 4; r++) { int i = tid + r*1024; sh[i] += v[r]; }
        __syncthreads();
    }
    for (int i = tid; i < N; i += 1024) g_rowoff[i+1] = sh[i];
    if (tid == 0) g_rowoff[0] = 0;
    for (int i = tid; i < N; i += 1024) {
        float d = (float)g_rowcnt[i];
        g_dinv[i] = (d > 0.0f) ? __fdiv_rn(1.0f, __fsqrt_rn(d)) : 0.0f;
    }
}

__global__ void k_fill(const int* e, int E) {
    int Eh = E >> 1;
    for (int j = blockIdx.x*blockDim.x + threadIdx.x; j < Eh; j += gridDim.x*blockDim.x) {
        int s = edge_at(e, j);
        int d = edge_at(e, E + j);
        int p = atomicAdd(&g_cursor[s], 1);
        g_cols[g_rowoff[s] + p] = d;
        int q = atomicAdd(&g_cursor[d], 1);
        g_cols[g_rowoff[d] + q] = s;
    }
}

// Write L from scratch; fused per-row lexmax; last block does argmax(0)+params.
// L[i][j] = (i==j) - (dinv_i*cnt)*dinv_j  (reference op order, RN)
__global__ void k_transform_rowmax() {
    __shared__ __align__(16) float cnt[N];   // 16KB
    __shared__ float sv[256];
    __shared__ int   si[256];
    int i = blockIdx.x, tid = threadIdx.x;
    for (int j = tid; j < N; j += 256) cnt[j] = 0.0f;
    __syncthreads();
    int s0 = g_rowoff[i], s1 = g_rowoff[i+1];
    for (int p = s0 + tid; p < s1; p += 256) atomicAdd(&cnt[g_cols[p]], 1.0f);
    __syncthreads();
    float di = g_dinv[i];
    float4* row = (float4*)(g_L + (size_t)i*N);
    const float4* dv4 = (const float4*)g_dinv;
    float best = -1.0f; int bcol = 0x7FFFFFFF;
    for (int t4 = tid; t4 < N/4; t4 += 256) {
        int j = t4*4;
        float4 dj = dv4[t4];
        float4 cv = *((float4*)&cnt[j]);
        float4 o;
        o.x = __fsub_rn((i==j  )?1.0f:0.0f, __fmul_rn(__fmul_rn(di, cv.x), dj.x));
        o.y = __fsub_rn((i==j+1)?1.0f:0.0f, __fmul_rn(__fmul_rn(di, cv.y), dj.y));
        o.z = __fsub_rn((i==j+2)?1.0f:0.0f, __fmul_rn(__fmul_rn(di, cv.z), dj.z));
        o.w = __fsub_rn((i==j+3)?1.0f:0.0f, __fmul_rn(__fmul_rn(di, cv.w), dj.w));
        row[t4] = o;
        if (j+0 > i) lexmax(best, bcol, fabsf(o.x), j+0);
        if (j+1 > i) lexmax(best, bcol, fabsf(o.y), j+1);
        if (j+2 > i) lexmax(best, bcol, fabsf(o.z), j+2);
        if (j+3 > i) lexmax(best, bcol, fabsf(o.w), j+3);
    }
    sv[tid] = best; si[tid] = bcol;
    __syncthreads();
    block_lexmax(sv, si, tid, 256);
    if (tid == 0) { g_rowval[i] = sv[0]; g_rowidx[i] = si[0]; }

    // last arriving block: argmax + params for iteration 0
    __shared__ bool isLast;
    if (tid == 0) {
        __threadfence();
        isLast = (atomicAdd(&g_arrT, 1u) == TB - 1u);
    }
    __syncthreads();
    if (!isLast) return;
    if (tid == 0) g_arrT = 0u;
    __threadfence();
    __syncthreads();
    argmax_and_params(0, sv, si, tid, 256);
}

// Two-sided rotation + incremental rowmax maintenance (bitwise-exact vs reference).
__global__ void k_rotate(int it) {
    int i = blockIdx.x*blockDim.x + threadIdx.x;
    if (i >= N) return;
    int k = g_rotk[it], l = g_rotl[it];
    float c = g_rotc[it], s = g_rots[it];
    if (i != k && i != l) {
        float ck = __ldcg(&g_L[i*N + k]), cl = __ldcg(&g_L[i*N + l]);
        float nk = __fsub_rn(__fmul_rn(c, ck), __fmul_rn(s, cl));
        float nl = __fadd_rn(__fmul_rn(s, ck), __fmul_rn(c, cl));
        g_L[i*N + k] = nk;
        g_L[i*N + l] = nl;
        float rk = __ldcg(&g_L[k*N + i]), rl = __ldcg(&g_L[l*N + i]);
        g_L[k*N + i] = __fsub_rn(__fmul_rn(c, rk), __fmul_rn(s, rl));
        g_L[l*N + i] = __fadd_rn(__fmul_rn(s, rk), __fmul_rn(c, rl));
        float bv = g_rowval[i]; int bj = g_rowidx[i];
        if (bj == k || bj == l) {
            int p = atomicAdd(&g_rn, 1);
            g_rlist[p] = i;
        } else {
            bool ch = false;
            if (k > i) { float a = fabsf(nk); if (a > bv || (a == bv && k < bj)) { bv = a; bj = k; ch = true; } }
            if (l > i) { float a = fabsf(nl); if (a > bv || (a == bv && l < bj)) { bv = a; bj = l; ch = true; } }
            if (ch) { g_rowval[i] = bv; g_rowidx[i] = bj; }
        }
    } else if (i == k) {
        float akk = __ldcg(&g_L[k*N + k]), akl = __ldcg(&g_L[k*N + l]);
        float alk = __ldcg(&g_L[l*N + k]), all = __ldcg(&g_L[l*N + l]);
        float akk1 = __fsub_rn(__fmul_rn(c, akk), __fmul_rn(s, akl));
        float akl1 = __fadd_rn(__fmul_rn(s, akk), __fmul_rn(c, akl));
        float alk1 = __fsub_rn(__fmul_rn(c, alk), __fmul_rn(s, all));
        float all1 = __fadd_rn(__fmul_rn(s, alk), __fmul_rn(c, all));
        float akk2 = __fsub_rn(__fmul_rn(c, akk1), __fmul_rn(s, alk1));
        float all2 = __fadd_rn(__fmul_rn(s, akl1), __fmul_rn(c, all1));
        g_L[k*N + k] = akk2;
        g_L[l*N + l] = all2;
        g_L[k*N + l] = 0.0f;
        g_L[l*N + k] = 0.0f;
        int p = atomicAdd(&g_rn, 2);
        g_rlist[p] = k; g_rlist[p+1] = l;
    }
}

// Rescan flagged rows; last arriving block performs argmax + params for iteration `it`.
__global__ void k_rescan_argmax(int it) {
    __shared__ float sv[256];
    __shared__ int   si[256];
    int tid = threadIdx.x;
    int nr = g_rn;
    for (int b = blockIdx.x; b < nr; b += RB) {
        int i = g_rlist[b];
        const float* rowp = g_L + (size_t)i*N;
        float best = -1.0f; int bcol = 0x7FFFFFFF;
        for (int j = i + 1 + tid; j < N; j += 256) {
            float a = fabsf(__ldcg(&rowp[j]));
            if (a > best || (a == best && j < bcol)) { best = a; bcol = j; }
        }
        sv[tid] = best; si[tid] = bcol;
        __syncthreads();
        block_lexmax(sv, si, tid, 256);
        if (tid == 0) { g_rowval[i] = sv[0]; g_rowidx[i] = si[0]; }
        __syncthreads();
    }
    __shared__ bool isLast;
    if (tid == 0) {
        __threadfence();
        isLast = (atomicAdd(&g_arrR, 1u) == RB - 1u);
    }
    __syncthreads();
    if (!isLast) return;
    if (tid == 0) g_arrR = 0u;
    __threadfence();
    __syncthreads();
    argmax_and_params(it, sv, si, tid, 256);
}

// ---------------- Cayley filter helper ----------------
__device__ __forceinline__ float g_entry(float wv, float hoi,
                                         const float* rw, const float* iw, float cval) {
    float hw = __fmul_rn(hoi, wv);
    float a2 = (hw > 1e-5f) ? 2.0f * atanf(__fdiv_rn(1.0f, hw)) : 2.0f;
    float acc = cval;
#pragma unroll
    for (int r = 0; r < RWR; r++) {
        float th = a2 * (float)(r + 1);
        float sn, cs;
        sincosf(th, &sn, &cs);
        acc += rw[r]*cs - iw[r]*sn;
    }
    return acc;
}

__global__ void k_G1(const float* h, const float* rw, const float* iw, const float* cc) {
    int t = blockIdx.x*blockDim.x + threadIdx.x;
    if (t < COUT*CIN) {
        int o = t >> 6, i = t & 63;
        int oi = o*CIN + i;
        g_G1[i*COUT + o] = g_entry(1.0f, h[oi], rw + oi*RWR, iw + oi*RWR, cc[oi]);
    }
}

__global__ void k_auxinit(const float* x) {
    const float4* xi = (const float4*)x;
    float4* ao = (float4*)g_aux;
    int t = blockIdx.x*blockDim.x + threadIdx.x;
    if (t < N*CIN/4) ao[t] = xi[t];
}

// aux = U^T x  (apply R1^T first)
__global__ void k_auxrot() {
    int o = threadIdx.x;
    for (int t = 0; t < ITERS; t++) {
        int k = g_rotk[t], l = g_rotl[t];
        float c = g_rotc[t], s = g_rots[t];
        float xk = g_aux[k*CIN + o], xl = g_aux[l*CIN + o];
        g_aux[k*CIN + o] = c*xk - s*xl;
        g_aux[l*CIN + o] = s*xk + c*xl;
    }
}

// gemm (inline special-node path, bias add) + last-block outrot
__global__ void k_gemm(const float* h, const float* rw, const float* iw,
                       const float* cc, const float* bias, float* out) {
    __shared__ float sa[4][CIN];
    int tid = threadIdx.x;
    int r = tid >> 6, o = tid & 63;
    int n = blockIdx.x*4 + r;
    sa[r][o] = g_aux[n*CIN + o];
    __syncthreads();
    float wv = g_L[(size_t)n*N + n];
    float acc = 0.0f;
    if (wv == 1.0f) {
#pragma unroll 16
        for (int i = 0; i < CIN; i++)
            acc = fmaf(g_G1[i*COUT + o], sa[r][i], acc);
    } else {
        for (int i = 0; i < CIN; i++) {
            int oi = o*CIN + i;
            acc = fmaf(g_entry(wv, h[oi], rw + oi*RWR, iw + oi*RWR, cc[oi]), sa[r][i], acc);
        }
    }
    out[n*COUT + o] = acc + bias[o];

    // last arriving block: rotate output rows (U * outT), bias-compensated (bias==0)
    __shared__ bool isLast;
    if (tid == 0) {
        __threadfence();
        isLast = (atomicAdd(&g_arrG, 1u) == gridDim.x - 1u);
    }
    __syncthreads();
    if (!isLast) return;
    if (tid == 0) g_arrG = 0u;
    __threadfence();
    __syncthreads();
    if (tid < COUT) {
        int oo = tid;
        float b = bias[oo];
        for (int t = ITERS - 1; t >= 0; t--) {
            int k = g_rotk[t], l = g_rotl[t];
            float c = g_rotc[t], s = g_rots[t];
            float vk = __ldcg(&out[k*COUT + oo]) - b;
            float vl = __ldcg(&out[l*COUT + oo]) - b;
            out[k*COUT + oo] =  c*vk + s*vl + b;
            out[l*COUT + oo] = -s*vk + c*vl + b;
        }
    }
}

// ---------------- launch ----------------
extern "C" void kernel_launch(void* const* d_in, const int* in_sizes, int n_in,
                              void* d_out, int out_size) {
    const float* x    = (const float*)d_in[0];
    const int*   e    = (const int*)  d_in[1];
    const float* rw   = (const float*)d_in[2];
    const float* iw   = (const float*)d_in[3];
    const float* h    = (const float*)d_in[4];
    const float* cc   = (const float*)d_in[5];
    const float* bias = (const float*)d_in[6];
    float* out = (float*)d_out;
    int E = in_sizes[1] / 2;   // edge_index shape (2, E)

    k_setup<<<16, 256>>>(e);
    k_G1<<<16, 256>>>(h, rw, iw, cc);
    k_auxinit<<<256, 256>>>(x);
    k_count<<<512, 256>>>(e, E);
    k_scan<<<1, 1024>>>();
    k_fill<<<512, 256>>>(e, E);
    k_transform_rowmax<<<TB, 256>>>();
    for (int it = 0; it < ITERS; it++) {
        k_rotate<<<16, 256>>>(it);
        if (it + 1 < ITERS) k_rescan_argmax<<<RB, 256>>>(it + 1);
    }
    k_auxrot<<<1, 64>>>();
    k_gemm<<<N/4, 256>>>(h, rw, iw, cc, bias, out);
}

// round 8
// speedup vs baseline: 1.1100x; 1.1042x over previous
#include <cuda_runtime.h>

#define N 4096
#define NN (N*N)
#define CIN 64
#define COUT 64
#define RWR 4
#define ITERS 10
#define BW 256          // bucket width (max supported row degree)

// ---------------- device scratch (static globals: no allocations) ----------------
__device__ __align__(16) float g_L[NN];       // 64MB Jacobi working matrix
__device__ int   g_cursor[N];                 // per-row fill cursor == degree
__device__ int   g_bucket[N*BW];              // 4MB fixed-width adjacency
__device__ __align__(16) float g_dinv[N];
__device__ __align__(16) float g_aux[N*CIN];
__device__ float g_G1[CIN*COUT];              // [i][o]
__device__ int   g_is64;
__device__ int   g_rotk[ITERS], g_rotl[ITERS];
__device__ float g_rotc[ITERS], g_rots[ITERS];
__device__ float g_rowval[N];
__device__ int   g_rowidx[N];
__device__ int   g_rlist[N];
__device__ int   g_rn;
__device__ unsigned g_arrG;

__device__ __forceinline__ int edge_at(const int* e, int j) {
    return g_is64 ? e[2*j] : e[j];      // int64: value in low word
}

__device__ __forceinline__ void lexmax(float& bv, int& bi, float v, int i) {
    if (v > bv || (v == bv && i < bi)) { bv = v; bi = i; }
}

__device__ __forceinline__ void block_lexmax(float* sv, int* si, int tid, int nthr) {
    for (int off = nthr/2; off > 0; off >>= 1) {
        if (tid < off) {
            float v = sv[tid+off]; int c = si[tid+off];
            if (v > sv[tid] || (v == sv[tid] && c < si[tid])) { sv[tid] = v; si[tid] = c; }
        }
        __syncthreads();
    }
}

// ---------------- setup ----------------
__global__ void k_setup(const int* e) {
    int t = blockIdx.x*blockDim.x + threadIdx.x;
    if (t < N) g_cursor[t] = 0;
    if (t == 0) {
        int nz = 0;
        for (int j = 1; j < 512; j += 2) nz |= (e[j] != 0);
        g_is64 = nz ? 0 : 1;
        g_rn = 0; g_arrG = 0u;
    }
}

// scatter all E directed edges into fixed-width buckets; cursor becomes degree
__global__ void k_bucket(const int* e, int E) {
    for (int j = blockIdx.x*blockDim.x + threadIdx.x; j < E; j += gridDim.x*blockDim.x) {
        int r = edge_at(e, j);
        int c = edge_at(e, E + j);
        int p = atomicAdd(&g_cursor[r], 1);
        if (p < BW) g_bucket[r*BW + p] = c;
    }
}

__global__ void k_dinv() {
    int t = blockIdx.x*blockDim.x + threadIdx.x;
    if (t < N) {
        float d = (float)g_cursor[t];
        g_dinv[t] = (d > 0.0f) ? __fdiv_rn(1.0f, __fsqrt_rn(d)) : 0.0f;
    }
}

// Write L from scratch (no 64MB zero/read): per-row shared counts from bucket.
// L[i][j] = (i==j) - (dinv_i*cnt)*dinv_j  (reference op order, RN). Fused per-row lexmax.
__global__ void k_transform_rowmax() {
    __shared__ __align__(16) float cnt[N];   // 16KB
    __shared__ float sv[256];
    __shared__ int   si[256];
    int i = blockIdx.x, tid = threadIdx.x;
    for (int j = tid; j < N; j += 256) cnt[j] = 0.0f;
    __syncthreads();
    int deg = g_cursor[i];
    for (int p = tid; p < deg; p += 256) atomicAdd(&cnt[g_bucket[i*BW + p]], 1.0f);
    __syncthreads();
    float di = g_dinv[i];
    float4* row = (float4*)(g_L + (size_t)i*N);
    const float4* dv4 = (const float4*)g_dinv;
    float best = -1.0f; int bcol = 0x7FFFFFFF;
    for (int t4 = tid; t4 < N/4; t4 += 256) {
        int j = t4*4;
        float4 dj = dv4[t4];
        float4 cv = *((float4*)&cnt[j]);
        float4 o;
        o.x = __fsub_rn((i==j  )?1.0f:0.0f, __fmul_rn(__fmul_rn(di, cv.x), dj.x));
        o.y = __fsub_rn((i==j+1)?1.0f:0.0f, __fmul_rn(__fmul_rn(di, cv.y), dj.y));
        o.z = __fsub_rn((i==j+2)?1.0f:0.0f, __fmul_rn(__fmul_rn(di, cv.z), dj.z));
        o.w = __fsub_rn((i==j+3)?1.0f:0.0f, __fmul_rn(__fmul_rn(di, cv.w), dj.w));
        row[t4] = o;
        if (j+0 > i) lexmax(best, bcol, fabsf(o.x), j+0);
        if (j+1 > i) lexmax(best, bcol, fabsf(o.y), j+1);
        if (j+2 > i) lexmax(best, bcol, fabsf(o.z), j+2);
        if (j+3 > i) lexmax(best, bcol, fabsf(o.w), j+3);
    }
    sv[tid] = best; si[tid] = bcol;
    __syncthreads();
    block_lexmax(sv, si, tid, 256);
    if (tid == 0) { g_rowval[i] = sv[0]; g_rowidx[i] = si[0]; }
}

// Global argmax over per-row maxima; rotation params for iteration `it` (reference RN path).
__global__ void k_argmax(int it) {
    int tid = threadIdx.x;
    __shared__ float sv[256];
    __shared__ int   si[256];
    float best = -1.0f; int bflat = 0x7FFFFFFF;
    for (int i = tid; i < N; i += 256) {
        float v = g_rowval[i];
        if (v >= 0.0f) {
            int flat = i*N + g_rowidx[i];
            if (v > best || (v == best && flat < bflat)) { best = v; bflat = flat; }
        }
    }
    sv[tid] = best; si[tid] = bflat;
    __syncthreads();
    block_lexmax(sv, si, tid, 256);
    if (tid == 0) {
        int idx = si[0];
        int k = idx >> 12, l = idx & (N-1);
        float akl = g_L[k*N + l];
        float akk = g_L[k*N + k];
        float all = g_L[l*N + l];
        float aDiff = __fsub_rn(all, akk);
        float akl_safe   = (akl   == 0.0f) ? 1.0f : akl;
        float aDiff_safe = (aDiff == 0.0f) ? 1.0f : aDiff;
        float phi = __fdiv_rn(aDiff, __fmul_rn(2.0f, akl_safe));
        float t2 = __fdiv_rn(1.0f, __fadd_rn(fabsf(phi),
                     __fsqrt_rn(__fadd_rn(__fmul_rn(phi, phi), 1.0f))));
        if (phi < 0.0f) t2 = -t2;
        float t1 = __fdiv_rn(akl, aDiff_safe);
        float tt = (fabsf(akl) < __fmul_rn(fabsf(aDiff), 1e-36f)) ? t1 : t2;
        float cv = __fdiv_rn(1.0f, __fsqrt_rn(__fadd_rn(__fmul_rn(tt, tt), 1.0f)));
        float ss = __fmul_rn(tt, cv);
        g_rotk[it] = k; g_rotl[it] = l; g_rotc[it] = cv; g_rots[it] = ss;
        g_rn = 0;
    }
}

// Two-sided rotation + incremental rowmax maintenance (bitwise-exact vs reference).
__global__ void k_rotate(int it) {
    int i = blockIdx.x*blockDim.x + threadIdx.x;
    if (i >= N) return;
    int k = g_rotk[it], l = g_rotl[it];
    float c = g_rotc[it], s = g_rots[it];
    if (i != k && i != l) {
        float ck = g_L[i*N + k], cl = g_L[i*N + l];
        float nk = __fsub_rn(__fmul_rn(c, ck), __fmul_rn(s, cl));
        float nl = __fadd_rn(__fmul_rn(s, ck), __fmul_rn(c, cl));
        g_L[i*N + k] = nk;
        g_L[i*N + l] = nl;
        float rk = g_L[k*N + i], rl = g_L[l*N + i];
        g_L[k*N + i] = __fsub_rn(__fmul_rn(c, rk), __fmul_rn(s, rl));
        g_L[l*N + i] = __fadd_rn(__fmul_rn(s, rk), __fmul_rn(c, rl));
        float bv = g_rowval[i]; int bj = g_rowidx[i];
        if (bj == k || bj == l) {
            int p = atomicAdd(&g_rn, 1);
            g_rlist[p] = i;
        } else {
            bool ch = false;
            if (k > i) { float a = fabsf(nk); if (a > bv || (a == bv && k < bj)) { bv = a; bj = k; ch = true; } }
            if (l > i) { float a = fabsf(nl); if (a > bv || (a == bv && l < bj)) { bv = a; bj = l; ch = true; } }
            if (ch) { g_rowval[i] = bv; g_rowidx[i] = bj; }
        }
    } else if (i == k) {
        float akk = g_L[k*N + k], akl = g_L[k*N + l];
        float alk = g_L[l*N + k], all = g_L[l*N + l];
        float akk1 = __fsub_rn(__fmul_rn(c, akk), __fmul_rn(s, akl));
        float akl1 = __fadd_rn(__fmul_rn(s, akk), __fmul_rn(c, akl));
        float alk1 = __fsub_rn(__fmul_rn(c, alk), __fmul_rn(s, all));
        float all1 = __fadd_rn(__fmul_rn(s, alk), __fmul_rn(c, all));
        float akk2 = __fsub_rn(__fmul_rn(c, akk1), __fmul_rn(s, alk1));
        float all2 = __fadd_rn(__fmul_rn(s, akl1), __fmul_rn(c, all1));
        g_L[k*N + k] = akk2;
        g_L[l*N + l] = all2;
        g_L[k*N + l] = 0.0f;
        g_L[l*N + k] = 0.0f;
        int p = atomicAdd(&g_rn, 2);
        g_rlist[p] = k; g_rlist[p+1] = l;
    }
}

// Full rescan of flagged rows (strict upper part only).
__global__ void k_recompute() {
    int tid = threadIdx.x;
    __shared__ float sv[256];
    __shared__ int   si[256];
    int nr = g_rn;
    for (int b = blockIdx.x; b < nr; b += gridDim.x) {
        int i = g_rlist[b];
        const float* row = g_L + (size_t)i*N;
        float best = -1.0f; int bcol = 0x7FFFFFFF;
        for (int j = i + 1 + tid; j < N; j += 256) {
            float a = fabsf(row[j]);
            if (a > best || (a == best && j < bcol)) { best = a; bcol = j; }
        }
        sv[tid] = best; si[tid] = bcol;
        __syncthreads();
        block_lexmax(sv, si, tid, 256);
        if (tid == 0) { g_rowval[i] = sv[0]; g_rowidx[i] = si[0]; }
        __syncthreads();
    }
}

// ---------------- Cayley filter helper ----------------
__device__ __forceinline__ float g_entry(float wv, float hoi,
                                         const float* rw, const float* iw, float cval) {
    float hw = __fmul_rn(hoi, wv);
    float a2 = (hw > 1e-5f) ? 2.0f * atanf(__fdiv_rn(1.0f, hw)) : 2.0f;
    float acc = cval;
#pragma unroll
    for (int r = 0; r < RWR; r++) {
        float th = a2 * (float)(r + 1);
        float sn, cs;
        sincosf(th, &sn, &cs);
        acc += rw[r]*cs - iw[r]*sn;
    }
    return acc;
}

__global__ void k_G1(const float* h, const float* rw, const float* iw, const float* cc) {
    int t = blockIdx.x*blockDim.x + threadIdx.x;
    if (t < COUT*CIN) {
        int o = t >> 6, i = t & 63;
        int oi = o*CIN + i;
        g_G1[i*COUT + o] = g_entry(1.0f, h[oi], rw + oi*RWR, iw + oi*RWR, cc[oi]);
    }
}

__global__ void k_auxinit(const float* x) {
    const float4* xi = (const float4*)x;
    float4* ao = (float4*)g_aux;
    int t = blockIdx.x*blockDim.x + threadIdx.x;
    if (t < N*CIN/4) ao[t] = xi[t];
}

// aux = U^T x  (apply R1^T first); each thread owns column o — no cross-thread deps
__global__ void k_auxrot() {
    int o = threadIdx.x;
    for (int t = 0; t < ITERS; t++) {
        int k = g_rotk[t], l = g_rotl[t];
        float c = g_rotc[t], s = g_rots[t];
        float xk = g_aux[k*CIN + o], xl = g_aux[l*CIN + o];
        g_aux[k*CIN + o] = c*xk - s*xl;
        g_aux[l*CIN + o] = s*xk + c*xl;
    }
}

// gemm (inline special-node path, bias add) + last-block outrot
__global__ void k_gemm(const float* h, const float* rw, const float* iw,
                       const float* cc, const float* bias, float* out) {
    __shared__ float sa[4][CIN];
    int tid = threadIdx.x;
    int r = tid >> 6, o = tid & 63;
    int n = blockIdx.x*4 + r;
    sa[r][o] = g_aux[n*CIN + o];
    __syncthreads();
    float wv = g_L[(size_t)n*N + n];
    float acc = 0.0f;
    if (wv == 1.0f) {
#pragma unroll 16
        for (int i = 0; i < CIN; i++)
            acc = fmaf(g_G1[i*COUT + o], sa[r][i], acc);
    } else {
        for (int i = 0; i < CIN; i++) {
            int oi = o*CIN + i;
            acc = fmaf(g_entry(wv, h[oi], rw + oi*RWR, iw + oi*RWR, cc[oi]), sa[r][i], acc);
        }
    }
    out[n*COUT + o] = acc + bias[o];

    // last arriving block: rotate output rows (U * outT), bias-compensated (bias==0)
    __shared__ bool isLast;
    if (tid == 0) {
        __threadfence();
        isLast = (atomicAdd(&g_arrG, 1u) == gridDim.x - 1u);
    }
    __syncthreads();
    if (!isLast) return;
    if (tid == 0) g_arrG = 0u;
    __threadfence();
    __syncthreads();
    if (tid < COUT) {
        int oo = tid;
        float b = bias[oo];
        for (int t = ITERS - 1; t >= 0; t--) {
            int k = g_rotk[t], l = g_rotl[t];
            float c = g_rotc[t], s = g_rots[t];
            float vk = __ldcg(&out[k*COUT + oo]) - b;
            float vl = __ldcg(&out[l*COUT + oo]) - b;
            out[k*COUT + oo] =  c*vk + s*vl + b;
            out[l*COUT + oo] = -s*vk + c*vl + b;
        }
    }
}

// ---------------- launch ----------------
extern "C" void kernel_launch(void* const* d_in, const int* in_sizes, int n_in,
                              void* d_out, int out_size) {
    const float* x    = (const float*)d_in[0];
    const int*   e    = (const int*)  d_in[1];
    const float* rw   = (const float*)d_in[2];
    const float* iw   = (const float*)d_in[3];
    const float* h    = (const float*)d_in[4];
    const float* cc   = (const float*)d_in[5];
    const float* bias = (const float*)d_in[6];
    float* out = (float*)d_out;
    int E = in_sizes[1] / 2;   // edge_index shape (2, E)

    k_setup<<<16, 256>>>(e);
    k_bucket<<<512, 256>>>(e, E);
    k_dinv<<<16, 256>>>();
    k_transform_rowmax<<<N, 256>>>();
    k_argmax<<<1, 256>>>(0);
    for (int it = 0; it < ITERS; it++) {
        k_rotate<<<16, 256>>>(it);
        if (it + 1 < ITERS) {
            k_recompute<<<256, 256>>>();
            k_argmax<<<1, 256>>>(it + 1);
        }
    }
    k_G1<<<16, 256>>>(h, rw, iw, cc);
    k_auxinit<<<256, 256>>>(x);
    k_auxrot<<<1, 64>>>();
    k_gemm<<<N/4, 256>>>(h, rw, iw, cc, bias, out);
}